// round 3
// baseline (speedup 1.0000x reference)
#include <cuda_runtime.h>
#include <cstdint>

// Problem constants
#define BB   4
#define SS   2048
#define DD   512
#define HH   8
#define HD   64
#define NTOK (BB*SS)          // 8192
#define QKV_N (3*DD)          // 1536
#define SCALE 0.125f          // HD^-0.5

// ---------------- scratch (__device__ globals) ------------------------------
static __device__ float g_q[BB*HH*SS*HD];              // 16 MB (SCALE applied)
static __device__ float g_k[BB*HH*SS*HD];              // 16 MB
static __device__ float g_v[BB*HH*SS*HD];              // 16 MB
static __device__ float g_ao[NTOK*DD];                 // 16 MB
static __device__ float g_l[BB*HH*SS];                 // softmax denominators
static __device__ float g_vs[BB*HH*HD];                // colsum of V per (b,h)

// ---------------- tf32 helpers ---------------------------------------------
__device__ __forceinline__ uint32_t f2tf32(float f) {
    uint32_t u;
    asm("cvt.rna.tf32.f32 %0, %1;" : "=r"(u) : "f"(f));
    return u;
}

__device__ __forceinline__ void mma_tf32(float* c,
                                         uint32_t a0, uint32_t a1, uint32_t a2, uint32_t a3,
                                         uint32_t b0, uint32_t b1) {
    asm volatile(
        "mma.sync.aligned.m16n8k8.row.col.f32.tf32.tf32.f32 "
        "{%0,%1,%2,%3}, {%4,%5,%6,%7}, {%8,%9}, {%0,%1,%2,%3};\n"
        : "+f"(c[0]), "+f"(c[1]), "+f"(c[2]), "+f"(c[3])
        : "r"(a0), "r"(a1), "r"(a2), "r"(a3), "r"(b0), "r"(b1));
}

// Stage a 64x64 fp32 tile (row stride ld floats) into tf32 smem [64][68].
__device__ __forceinline__ void stage_tile(uint32_t (*S)[68], const float* __restrict__ src,
                                           size_t ld, int tid) {
    for (int f = tid; f < 1024; f += 256) {
        int r = f >> 4, c = (f & 15) << 2;
        float4 v = *(const float4*)&src[(size_t)r * ld + c];
        uint4 u;
        u.x = f2tf32(v.x); u.y = f2tf32(v.y); u.z = f2tf32(v.z); u.w = f2tf32(v.w);
        *(uint4*)&S[r][c] = u;
    }
}

// ============================================================================
// Shared score block: computes premixed logits L[j][16] (j = post-mix head)
// for the (qt, kt) 64x64 tile, summing over the 8 raw heads.
// IDENTICAL code is used by pass 1 and pass 2 so L is bitwise reproducible.
// ============================================================================
__device__ __forceinline__ void score_block(uint32_t (*sQ)[68], uint32_t (*sK)[68],
                                            const float* __restrict__ s_wl,
                                            int b, int qt, int kt, int tid,
                                            float L[8][16]) {
    const int lane = tid & 31, warp = tid >> 5;
    const int g = lane >> 2, t = lane & 3;
    const int q0 = (warp >> 1) * 16, n0c = (warp & 1) * 32;

    for (int h = 0; h < 8; h++) {
        __syncthreads();
        stage_tile(sQ, &g_q[(((size_t)b*HH + h)*SS + qt)*HD], HD, tid);
        stage_tile(sK, &g_k[(((size_t)b*HH + h)*SS + kt)*HD], HD, tid);
        __syncthreads();
        float S[16];
        #pragma unroll
        for (int e = 0; e < 16; e++) S[e] = 0.f;
        #pragma unroll
        for (int kk = 0; kk < 64; kk += 8) {
            uint32_t a0 = sQ[q0 + g][kk + t];
            uint32_t a1 = sQ[q0 + g + 8][kk + t];
            uint32_t a2 = sQ[q0 + g][kk + t + 4];
            uint32_t a3 = sQ[q0 + g + 8][kk + t + 4];
            #pragma unroll
            for (int jt = 0; jt < 4; jt++) {
                uint32_t b0 = sK[n0c + 8*jt + g][kk + t];
                uint32_t b1 = sK[n0c + 8*jt + g][kk + t + 4];
                mma_tf32(&S[jt*4], a0, a1, a2, a3, b0, b1);
            }
        }
        #pragma unroll
        for (int j = 0; j < 8; j++) {
            float wv = s_wl[j*8 + h];
            #pragma unroll
            for (int e = 0; e < 16; e++) L[j][e] += wv * S[e];
        }
    }
}

// ============================================================================
// Kernel 1: QKV GEMM (tf32 mma), epilogue scatters to g_q/g_k/g_v.
// ============================================================================
__global__ __launch_bounds__(256) void k_qkv(const float* __restrict__ x,
                                             const float* __restrict__ w) {
    __shared__ uint32_t As[64][68];
    __shared__ uint32_t Bs[64][68];
    const int tid = threadIdx.x;
    const int lane = tid & 31, warp = tid >> 5;
    const int g = lane >> 2, t = lane & 3;
    const int q0 = (warp >> 1) * 16, n0c = (warp & 1) * 32;
    const int m0 = blockIdx.y * 64;
    const int n0 = blockIdx.x * 64;

    float c[4][4] = {};
    for (int k0 = 0; k0 < DD; k0 += 64) {
        stage_tile(As, &x[(size_t)m0 * DD + k0], DD, tid);
        stage_tile(Bs, &w[(size_t)n0 * DD + k0], DD, tid);
        __syncthreads();
        #pragma unroll
        for (int kk = 0; kk < 64; kk += 8) {
            uint32_t a0 = As[q0 + g][kk + t];
            uint32_t a1 = As[q0 + g + 8][kk + t];
            uint32_t a2 = As[q0 + g][kk + t + 4];
            uint32_t a3 = As[q0 + g + 8][kk + t + 4];
            #pragma unroll
            for (int j = 0; j < 4; j++) {
                uint32_t b0 = Bs[n0c + 8*j + g][kk + t];
                uint32_t b1 = Bs[n0c + 8*j + g][kk + t + 4];
                mma_tf32(c[j], a0, a1, a2, a3, b0, b1);
            }
        }
        __syncthreads();
    }
    const int which = n0 >> 9;
    const int h     = (n0 >> 6) & 7;
    const int b     = m0 / SS;
    const int sbase = m0 % SS;
    float* dst = (which == 0) ? g_q : (which == 1) ? g_k : g_v;
    const float mul = (which == 0) ? SCALE : 1.0f;
    #pragma unroll
    for (int j = 0; j < 4; j++) {
        int col = n0c + 8*j + 2*t;
        float2 lo = make_float2(c[j][0]*mul, c[j][1]*mul);
        float2 hi = make_float2(c[j][2]*mul, c[j][3]*mul);
        *(float2*)&dst[(((size_t)b*HH + h)*SS + sbase + q0 + g    )*HD + col] = lo;
        *(float2*)&dst[(((size_t)b*HH + h)*SS + sbase + q0 + g + 8)*HD + col] = hi;
    }
}

// ============================================================================
// Kernel 2: V column sums (for the b_w bias term). grid = BB*HH, 256 thr.
// ============================================================================
__global__ __launch_bounds__(256) void k_vsum() {
    __shared__ float red[4][64];
    const int tid = threadIdx.x;
    const int bh = blockIdx.x;
    const int d = tid & 63, seg = tid >> 6;
    const float* vp = &g_v[(size_t)bh * SS * HD];
    float s = 0.f;
    for (int r = seg*512; r < (seg+1)*512; r++) s += vp[(size_t)r*HD + d];
    red[seg][d] = s;
    __syncthreads();
    if (tid < 64)
        g_vs[(size_t)bh*HD + tid] = red[0][tid] + red[1][tid] + red[2][tid] + red[3][tid];
}

// ============================================================================
// Kernel 3 (pass 1): softmax denominators l_j[q] = sum_k exp(L_j + b_l).
// grid (SS/64, BB). Register-resident l accumulators, one reduction at end.
// ============================================================================
__global__ __launch_bounds__(256, 1) void k_stats(const float* __restrict__ wl,
                                                  const float* __restrict__ bl) {
    __shared__ uint32_t sQ[64][68];
    __shared__ uint32_t sK[64][68];
    __shared__ float s_wl[64];
    __shared__ float s_l[8][64];
    const int tid = threadIdx.x;
    const int lane = tid & 31, warp = tid >> 5;
    const int g = lane >> 2, t = lane & 3;
    const int q0 = (warp >> 1) * 16;
    const int qt = blockIdx.x * 64;
    const int b  = blockIdx.y;

    if (tid < 64) s_wl[tid] = wl[tid];
    for (int i = tid; i < 512; i += 256) s_l[i >> 6][i & 63] = 0.f;

    float blr[8];
    #pragma unroll
    for (int j = 0; j < 8; j++) blr[j] = __ldg(&bl[j]);

    float lacc[8][2];
    #pragma unroll
    for (int j = 0; j < 8; j++) { lacc[j][0] = 0.f; lacc[j][1] = 0.f; }

    for (int kt = 0; kt < SS; kt += 64) {
        float L[8][16];
        #pragma unroll
        for (int j = 0; j < 8; j++)
            #pragma unroll
            for (int e = 0; e < 16; e++) L[j][e] = 0.f;
        score_block(sQ, sK, s_wl, b, qt, kt, tid, L);
        #pragma unroll
        for (int j = 0; j < 8; j++) {
            #pragma unroll
            for (int jt = 0; jt < 4; jt++) {
                lacc[j][0] += __expf(L[j][jt*4+0] + blr[j]) + __expf(L[j][jt*4+1] + blr[j]);
                lacc[j][1] += __expf(L[j][jt*4+2] + blr[j]) + __expf(L[j][jt*4+3] + blr[j]);
            }
        }
    }
    // reduce: over t lanes (shfl), then over warp-pairs (smem atomics)
    #pragma unroll
    for (int j = 0; j < 8; j++) {
        #pragma unroll
        for (int rr = 0; rr < 2; rr++) {
            float v = lacc[j][rr];
            v += __shfl_xor_sync(0xffffffffu, v, 1);
            v += __shfl_xor_sync(0xffffffffu, v, 2);
            if (t == 0) atomicAdd(&s_l[j][q0 + g + 8*rr], v);
        }
    }
    __syncthreads();
    for (int i = tid; i < 512; i += 256)
        g_l[((size_t)b*HH + (i >> 6))*SS + qt + (i & 63)] = s_l[i >> 6][i & 63];
}

// ============================================================================
// Kernel 4 (pass 2): fused scores -> softmax -> post-mix -> AV.
// grid (SS/64, BB). Dynamic smem: O accum 128KB + W/Q/K tiles + inv_l.
// ============================================================================
#define OFF_W   131072
#define OFF_Q   148480
#define OFF_K   165888
#define OFF_INV 183296
#define SMEM_FUSED (183296 + 2048)

__global__ __launch_bounds__(256, 1) void k_fused(const float* __restrict__ wl,
                                                  const float* __restrict__ bl,
                                                  const float* __restrict__ ww,
                                                  const float* __restrict__ bw) {
    extern __shared__ char dsm[];
    float*    sO = (float*)dsm;                              // [8][64][64]
    uint32_t (*sW)[68] = (uint32_t(*)[68])(dsm + OFF_W);
    uint32_t (*sQ)[68] = (uint32_t(*)[68])(dsm + OFF_Q);
    uint32_t (*sK)[68] = (uint32_t(*)[68])(dsm + OFF_K);     // also V staging
    float* s_inv = (float*)(dsm + OFF_INV);                  // [8][64]
    __shared__ float s_wl[64];
    __shared__ float s_ww[64];
    __shared__ float s_bw[8];

    const int tid = threadIdx.x;
    const int lane = tid & 31, warp = tid >> 5;
    const int g = lane >> 2, t = lane & 3;
    const int q0 = (warp >> 1) * 16, n0c = (warp & 1) * 32;
    const int qt = blockIdx.x * 64;
    const int b  = blockIdx.y;
    const int r0 = q0 + g, r1 = r0 + 8;

    for (int i = tid; i < 32768; i += 256) sO[i] = 0.f;
    if (tid < 64) { s_wl[tid] = wl[tid]; s_ww[tid] = ww[tid]; }
    if (tid < 8)  s_bw[tid] = bw[tid];
    for (int i = tid; i < 512; i += 256)
        s_inv[i] = 1.0f / g_l[((size_t)b*HH + (i >> 6))*SS + qt + (i & 63)];

    float blr[8];
    #pragma unroll
    for (int j = 0; j < 8; j++) blr[j] = __ldg(&bl[j]);

    __syncthreads();
    float inv0[8], inv1[8];
    #pragma unroll
    for (int j = 0; j < 8; j++) { inv0[j] = s_inv[j*64 + r0]; inv1[j] = s_inv[j*64 + r1]; }

    for (int kt = 0; kt < SS; kt += 64) {
        float L[8][16];
        #pragma unroll
        for (int j = 0; j < 8; j++)
            #pragma unroll
            for (int e = 0; e < 16; e++) L[j][e] = 0.f;
        score_block(sQ, sK, s_wl, b, qt, kt, tid, L);

        // normalized probabilities: P_j = exp(L + b_l)/l_j (in place)
        #pragma unroll
        for (int j = 0; j < 8; j++) {
            #pragma unroll
            for (int jt = 0; jt < 4; jt++) {
                L[j][jt*4+0] = __expf(L[j][jt*4+0] + blr[j]) * inv0[j];
                L[j][jt*4+1] = __expf(L[j][jt*4+1] + blr[j]) * inv0[j];
                L[j][jt*4+2] = __expf(L[j][jt*4+2] + blr[j]) * inv1[j];
                L[j][jt*4+3] = __expf(L[j][jt*4+3] + blr[j]) * inv1[j];
            }
        }

        // per output head g: W_g = sum_j w_w[g,j] P_j ; then O_g += W_g @ V_g
        for (int gg = 0; gg < 8; gg++) {
            float wwg[8];
            #pragma unroll
            for (int j = 0; j < 8; j++) wwg[j] = s_ww[gg*8 + j];
            float w[16];
            #pragma unroll
            for (int e = 0; e < 16; e++) {
                float acc = 0.f;
                #pragma unroll
                for (int j = 0; j < 8; j++) acc += wwg[j] * L[j][e];
                w[e] = acc;
            }
            __syncthreads();  // previous gg's mma done with sW/sK
            #pragma unroll
            for (int jt = 0; jt < 4; jt++) {
                int c = n0c + 8*jt + 2*t;
                sW[r0][c]   = f2tf32(w[jt*4+0]);
                sW[r0][c+1] = f2tf32(w[jt*4+1]);
                sW[r1][c]   = f2tf32(w[jt*4+2]);
                sW[r1][c+1] = f2tf32(w[jt*4+3]);
            }
            stage_tile(sK, &g_v[(((size_t)b*HH + gg)*SS + kt)*HD], HD, tid);
            __syncthreads();
            float o[16];
            #pragma unroll
            for (int e = 0; e < 16; e++) o[e] = 0.f;
            #pragma unroll
            for (int kk = 0; kk < 64; kk += 8) {
                uint32_t a0 = sW[q0 + g][kk + t];
                uint32_t a1 = sW[q0 + g + 8][kk + t];
                uint32_t a2 = sW[q0 + g][kk + t + 4];
                uint32_t a3 = sW[q0 + g + 8][kk + t + 4];
                #pragma unroll
                for (int jt = 0; jt < 4; jt++) {
                    uint32_t b0 = sK[kk + t][n0c + 8*jt + g];
                    uint32_t b1 = sK[kk + t + 4][n0c + 8*jt + g];
                    mma_tf32(&o[jt*4], a0, a1, a2, a3, b0, b1);
                }
            }
            float* Og = sO + gg*4096;
            #pragma unroll
            for (int jt = 0; jt < 4; jt++) {
                int c = n0c + 8*jt + 2*t;
                Og[r0*64 + c]     += o[jt*4+0];
                Og[r0*64 + c + 1] += o[jt*4+1];
                Og[r1*64 + c]     += o[jt*4+2];
                Og[r1*64 + c + 1] += o[jt*4+3];
            }
        }
    }

    // epilogue: + b_w[g] * colsum(V_g), write to g_ao[b, q, g*64+d]
    __syncthreads();
    for (int i = tid; i < 32768; i += 256) {
        int gg = i >> 12, q = (i >> 6) & 63, d = i & 63;
        float vs = g_vs[((size_t)b*HH + gg)*HD + d];
        g_ao[((size_t)b*SS + qt + q)*DD + gg*64 + d] = sO[i] + s_bw[gg]*vs;
    }
}

// ============================================================================
// Kernel 5: output projection (tf32 mma).
// ============================================================================
__global__ __launch_bounds__(256) void k_proj(const float* __restrict__ w,
                                              const float* __restrict__ bias,
                                              float* __restrict__ out) {
    __shared__ uint32_t As[64][68];
    __shared__ uint32_t Bs[64][68];
    const int tid = threadIdx.x;
    const int lane = tid & 31, warp = tid >> 5;
    const int g = lane >> 2, t = lane & 3;
    const int q0 = (warp >> 1) * 16, n0c = (warp & 1) * 32;
    const int m0 = blockIdx.y * 64;
    const int n0 = blockIdx.x * 64;

    float c[4][4] = {};
    for (int k0 = 0; k0 < DD; k0 += 64) {
        stage_tile(As, &g_ao[(size_t)m0 * DD + k0], DD, tid);
        stage_tile(Bs, &w[(size_t)n0 * DD + k0], DD, tid);
        __syncthreads();
        #pragma unroll
        for (int kk = 0; kk < 64; kk += 8) {
            uint32_t a0 = As[q0 + g][kk + t];
            uint32_t a1 = As[q0 + g + 8][kk + t];
            uint32_t a2 = As[q0 + g][kk + t + 4];
            uint32_t a3 = As[q0 + g + 8][kk + t + 4];
            #pragma unroll
            for (int j = 0; j < 4; j++) {
                uint32_t b0 = Bs[n0c + 8*j + g][kk + t];
                uint32_t b1 = Bs[n0c + 8*j + g][kk + t + 4];
                mma_tf32(c[j], a0, a1, a2, a3, b0, b1);
            }
        }
        __syncthreads();
    }
    #pragma unroll
    for (int j = 0; j < 4; j++) {
        int col = n0 + n0c + 8*j + 2*t;
        float2 bv = *(const float2*)&bias[col];
        float2 lo = make_float2(c[j][0] + bv.x, c[j][1] + bv.y);
        float2 hi = make_float2(c[j][2] + bv.x, c[j][3] + bv.y);
        *(float2*)&out[(size_t)(m0 + q0 + g    ) * DD + col] = lo;
        *(float2*)&out[(size_t)(m0 + q0 + g + 8) * DD + col] = hi;
    }
}

// ============================================================================
extern "C" void kernel_launch(void* const* d_in, const int* in_sizes, int n_in,
                              void* d_out, int out_size) {
    const float* x      = (const float*)d_in[0];
    const float* w_qkv  = (const float*)d_in[1];
    const float* w_proj = (const float*)d_in[2];
    const float* b_proj = (const float*)d_in[3];
    const float* w_l    = (const float*)d_in[4];
    const float* b_l    = (const float*)d_in[5];
    const float* w_w    = (const float*)d_in[6];
    const float* b_w    = (const float*)d_in[7];
    float* out = (float*)d_out;

    cudaFuncSetAttribute(k_fused, cudaFuncAttributeMaxDynamicSharedMemorySize, SMEM_FUSED);

    k_qkv  <<<dim3(QKV_N/64, NTOK/64), 256>>>(x, w_qkv);
    k_vsum <<<BB*HH, 256>>>();
    k_stats<<<dim3(SS/64, BB), 256>>>(w_l, b_l);
    k_fused<<<dim3(SS/64, BB), 256, SMEM_FUSED>>>(w_l, b_l, w_w, b_w);
    k_proj <<<dim3(DD/64, NTOK/64), 256>>>(w_proj, b_proj, out);
}

// round 4
// speedup vs baseline: 1.1206x; 1.1206x over previous
#include <cuda_runtime.h>
#include <cuda_bf16.h>
#include <cstdint>

// Problem constants
#define BB   4
#define SS   2048
#define DD   512
#define HH   8
#define HD   64
#define NTOK (BB*SS)          // 8192
#define QKV_N (3*DD)          // 1536
#define SCALE 0.125f          // HD^-0.5

// ---------------- scratch (__device__ globals) ------------------------------
static __device__ float    g_q[BB*HH*SS*HD];           // 16 MB (SCALE applied)
static __device__ float    g_k[BB*HH*SS*HD];           // 16 MB
static __device__ float    g_v[BB*HH*SS*HD];           // 16 MB
static __device__ uint32_t g_vb[BB*HH*(SS/2)*HD];      // 8 MB  [b][h][kpair][d] bf16x2
static __device__ float    g_sc[134217728];            // premixed logits L, 512 MB
static __device__ float    g_ao[NTOK*DD];              // 16 MB
static __device__ float    g_l[BB*HH*SS];              // softmax denominators
static __device__ float    g_vs[BB*HH*HD];             // colsum of V per (b,h)

// ---------------- helpers ---------------------------------------------------
__device__ __forceinline__ uint32_t f2tf32(float f) {
    uint32_t u;
    asm("cvt.rna.tf32.f32 %0, %1;" : "=r"(u) : "f"(f));
    return u;
}

__device__ __forceinline__ void mma_tf32(float* c,
                                         uint32_t a0, uint32_t a1, uint32_t a2, uint32_t a3,
                                         uint32_t b0, uint32_t b1) {
    asm volatile(
        "mma.sync.aligned.m16n8k8.row.col.f32.tf32.tf32.f32 "
        "{%0,%1,%2,%3}, {%4,%5,%6,%7}, {%8,%9}, {%0,%1,%2,%3};\n"
        : "+f"(c[0]), "+f"(c[1]), "+f"(c[2]), "+f"(c[3])
        : "r"(a0), "r"(a1), "r"(a2), "r"(a3), "r"(b0), "r"(b1));
}

__device__ __forceinline__ void mma_bf16(float* c,
                                         uint32_t a0, uint32_t a1, uint32_t a2, uint32_t a3,
                                         uint32_t b0, uint32_t b1) {
    asm volatile(
        "mma.sync.aligned.m16n8k16.row.col.f32.bf16.bf16.f32 "
        "{%0,%1,%2,%3}, {%4,%5,%6,%7}, {%8,%9}, {%0,%1,%2,%3};\n"
        : "+f"(c[0]), "+f"(c[1]), "+f"(c[2]), "+f"(c[3])
        : "r"(a0), "r"(a1), "r"(a2), "r"(a3), "r"(b0), "r"(b1));
}

__device__ __forceinline__ uint32_t pack_bf16(float lo, float hi) {
    __nv_bfloat162 p = __floats2bfloat162_rn(lo, hi);   // .x = lo (low 16 bits)
    return *reinterpret_cast<uint32_t*>(&p);
}

// Stage a 64x64 fp32 tile (row stride ld floats) into tf32 smem [64][68].
__device__ __forceinline__ void stage_tile(uint32_t (*S)[68], const float* __restrict__ src,
                                           size_t ld, int tid) {
    for (int f = tid; f < 1024; f += 256) {
        int r = f >> 4, c = (f & 15) << 2;
        float4 v = *(const float4*)&src[(size_t)r * ld + c];
        uint4 u;
        u.x = f2tf32(v.x); u.y = f2tf32(v.y); u.z = f2tf32(v.z); u.w = f2tf32(v.w);
        *(uint4*)&S[r][c] = u;
    }
}

// ============================================================================
// Kernel 1: QKV GEMM (tf32 mma), epilogue scatters to g_q/g_k/g_v.
// ============================================================================
__global__ __launch_bounds__(256) void k_qkv(const float* __restrict__ x,
                                             const float* __restrict__ w) {
    __shared__ uint32_t As[64][68];
    __shared__ uint32_t Bs[64][68];
    const int tid = threadIdx.x;
    const int lane = tid & 31, warp = tid >> 5;
    const int g = lane >> 2, t = lane & 3;
    const int q0 = (warp >> 1) * 16, n0c = (warp & 1) * 32;
    const int m0 = blockIdx.y * 64;
    const int n0 = blockIdx.x * 64;

    float c[4][4] = {};
    for (int k0 = 0; k0 < DD; k0 += 64) {
        stage_tile(As, &x[(size_t)m0 * DD + k0], DD, tid);
        stage_tile(Bs, &w[(size_t)n0 * DD + k0], DD, tid);
        __syncthreads();
        #pragma unroll
        for (int kk = 0; kk < 64; kk += 8) {
            uint32_t a0 = As[q0 + g][kk + t];
            uint32_t a1 = As[q0 + g + 8][kk + t];
            uint32_t a2 = As[q0 + g][kk + t + 4];
            uint32_t a3 = As[q0 + g + 8][kk + t + 4];
            #pragma unroll
            for (int j = 0; j < 4; j++) {
                uint32_t b0 = Bs[n0c + 8*j + g][kk + t];
                uint32_t b1 = Bs[n0c + 8*j + g][kk + t + 4];
                mma_tf32(c[j], a0, a1, a2, a3, b0, b1);
            }
        }
        __syncthreads();
    }
    const int which = n0 >> 9;
    const int h     = (n0 >> 6) & 7;
    const int b     = m0 / SS;
    const int sbase = m0 % SS;
    float* dst = (which == 0) ? g_q : (which == 1) ? g_k : g_v;
    const float mul = (which == 0) ? SCALE : 1.0f;
    #pragma unroll
    for (int j = 0; j < 4; j++) {
        int col = n0c + 8*j + 2*t;
        float2 lo = make_float2(c[j][0]*mul, c[j][1]*mul);
        float2 hi = make_float2(c[j][2]*mul, c[j][3]*mul);
        *(float2*)&dst[(((size_t)b*HH + h)*SS + sbase + q0 + g    )*HD + col] = lo;
        *(float2*)&dst[(((size_t)b*HH + h)*SS + sbase + q0 + g + 8)*HD + col] = hi;
    }
}

// ============================================================================
// Kernel 2a: zero the softmax-denominator accumulator.
// ============================================================================
__global__ __launch_bounds__(256) void k_zero() {
    int i = blockIdx.x * 256 + threadIdx.x;
    if (i < BB*HH*SS) g_l[i] = 0.f;
}

// ============================================================================
// Kernel 2b: V column sums (for the b_w bias term). grid = BB*HH.
// ============================================================================
__global__ __launch_bounds__(256) void k_vsum() {
    __shared__ float red[4][64];
    const int tid = threadIdx.x;
    const int bh = blockIdx.x;
    const int d = tid & 63, seg = tid >> 6;
    const float* vp = &g_v[(size_t)bh * SS * HD];
    float s = 0.f;
    for (int r = seg*512; r < (seg+1)*512; r++) s += vp[(size_t)r*HD + d];
    red[seg][d] = s;
    __syncthreads();
    if (tid < 64)
        g_vs[(size_t)bh*HD + tid] = red[0][tid] + red[1][tid] + red[2][tid] + red[3][tid];
}

// ============================================================================
// Kernel 2c: pack V into bf16 k-pairs: g_vb[b][h][kp][d] = {V[2kp][d], V[2kp+1][d]}
// ============================================================================
__global__ __launch_bounds__(256) void k_packv() {
    int m = blockIdx.x * 256 + threadIdx.x;          // total 2M items
    if (m >= BB*HH*(SS/2)*HD) return;
    int d  = m & 63;
    int kp = (m >> 6) & (SS/2 - 1);
    int bh = m >> 16;
    float lo = g_v[((size_t)bh*SS + 2*kp    )*HD + d];
    float hi = g_v[((size_t)bh*SS + 2*kp + 1)*HD + d];
    g_vb[m] = pack_bf16(lo, hi);
}

// ============================================================================
// Kernel 3: scores + pre-softmax mix (tf32), stores L = premix + b_l, and
// atomically accumulates softmax denominators l_j[q] = sum_k exp(L).
// ============================================================================
__global__ __launch_bounds__(256, 1) void k_scores(const float* __restrict__ wl,
                                                   const float* __restrict__ bl) {
    __shared__ uint32_t Qs[64][68];
    __shared__ uint32_t Ks[64][68];
    __shared__ float s_wl[64];
    const int tid = threadIdx.x;
    const int lane = tid & 31, warp = tid >> 5;
    const int g = lane >> 2, t = lane & 3;
    const int q0 = (warp >> 1) * 16, n0c = (warp & 1) * 32;
    const int kt = blockIdx.x * 64;
    const int qt = blockIdx.y * 64;
    const int b  = blockIdx.z;

    if (tid < 64) s_wl[tid] = wl[tid];

    float blr[8];
    #pragma unroll
    for (int j = 0; j < 8; j++) blr[j] = __ldg(&bl[j]);

    float acc[8][16];
    #pragma unroll
    for (int gg = 0; gg < 8; gg++)
        #pragma unroll
        for (int e = 0; e < 16; e++) acc[gg][e] = 0.f;

    for (int h = 0; h < 8; h++) {
        __syncthreads();
        stage_tile(Qs, &g_q[(((size_t)b*HH + h)*SS + qt)*HD], HD, tid);
        stage_tile(Ks, &g_k[(((size_t)b*HH + h)*SS + kt)*HD], HD, tid);
        __syncthreads();
        float s[16] = {};
        #pragma unroll
        for (int kk = 0; kk < 64; kk += 8) {
            uint32_t a0 = Qs[q0 + g][kk + t];
            uint32_t a1 = Qs[q0 + g + 8][kk + t];
            uint32_t a2 = Qs[q0 + g][kk + t + 4];
            uint32_t a3 = Qs[q0 + g + 8][kk + t + 4];
            #pragma unroll
            for (int jt = 0; jt < 4; jt++) {
                uint32_t b0 = Ks[n0c + 8*jt + g][kk + t];
                uint32_t b1 = Ks[n0c + 8*jt + g][kk + t + 4];
                mma_tf32(&s[jt*4], a0, a1, a2, a3, b0, b1);
            }
        }
        #pragma unroll
        for (int j = 0; j < 8; j++) {
            float wv = s_wl[j*8 + h];
            #pragma unroll
            for (int e = 0; e < 16; e++) acc[j][e] += wv * s[e];
        }
    }
    // epilogue: add b_l, store L, accumulate exp-sums
    #pragma unroll
    for (int j = 0; j < 8; j++) {
        float blv = blr[j];
        size_t base = ((size_t)b*HH + j)*SS;
        float l0 = 0.f, l1 = 0.f;
        #pragma unroll
        for (int jt = 0; jt < 4; jt++) {
            int col = kt + n0c + 8*jt + 2*t;
            float v0 = acc[j][jt*4+0] + blv;
            float v1 = acc[j][jt*4+1] + blv;
            float v2 = acc[j][jt*4+2] + blv;
            float v3 = acc[j][jt*4+3] + blv;
            *(float2*)&g_sc[(base + qt + q0 + g    )*SS + col] = make_float2(v0, v1);
            *(float2*)&g_sc[(base + qt + q0 + g + 8)*SS + col] = make_float2(v2, v3);
            l0 += __expf(v0) + __expf(v1);
            l1 += __expf(v2) + __expf(v3);
        }
        // reduce over t lanes (quad), then atomic into global
        l0 += __shfl_xor_sync(0xffffffffu, l0, 1);
        l0 += __shfl_xor_sync(0xffffffffu, l0, 2);
        l1 += __shfl_xor_sync(0xffffffffu, l1, 1);
        l1 += __shfl_xor_sync(0xffffffffu, l1, 2);
        if (t == 0) {
            atomicAdd(&g_l[base + qt + q0 + g    ], l0);
            atomicAdd(&g_l[base + qt + q0 + g + 8], l1);
        }
    }
}

// ============================================================================
// Kernel 4: fused softmax + post-mix + AV (bf16 tensor cores).
// CTA per (b, qt64). L streamed from global directly to registers.
// smem: sO f32[8][64][65] | sV u32[8][64][33] | sW u32[2][64][33] | inv | ww | bw
// ============================================================================
#define AV_SV   133120
#define AV_SW   200704
#define AV_INV  217600
#define AV_WW   219648
#define AV_BW   219904
#define SMEM_AV 220160

__global__ __launch_bounds__(256, 1) void k_av_fused(const float* __restrict__ ww,
                                                     const float* __restrict__ bw) {
    extern __shared__ char dsm[];
    float*    sO   = (float*)dsm;                       // [8][64][65]
    uint32_t* sV   = (uint32_t*)(dsm + AV_SV);          // [8][64][33]  (d, kpair)
    uint32_t* sW   = (uint32_t*)(dsm + AV_SW);          // [2][64][33]  (q, kpair)
    float*    sinv = (float*)(dsm + AV_INV);            // [8][64]
    float*    sww  = (float*)(dsm + AV_WW);             // [8][8]
    float*    sbw  = (float*)(dsm + AV_BW);             // [8]

    const int tid = threadIdx.x;
    const int lane = tid & 31, warp = tid >> 5;
    const int g = lane >> 2, t = lane & 3;
    const int q0 = (warp >> 1) * 16, n0c = (warp & 1) * 32;
    const int qt = blockIdx.x * 64;
    const int b  = blockIdx.y;
    const int r0 = q0 + g, r1 = r0 + 8;

    for (int i = tid; i < 8*64*65; i += 256) sO[i] = 0.f;
    if (tid < 64) sww[tid] = ww[tid];
    if (tid < 8)  sbw[tid] = bw[tid];
    for (int i = tid; i < 512; i += 256)
        sinv[i] = 1.0f / g_l[((size_t)b*HH + (i >> 6))*SS + qt + (i & 63)];
    __syncthreads();

    float inv0[8], inv1[8];
    #pragma unroll
    for (int j = 0; j < 8; j++) { inv0[j] = sinv[j*64 + r0]; inv1[j] = sinv[j*64 + r1]; }

    int buf = 0;
    for (int kt = 0; kt < SS; kt += 64) {
        __syncthreads();    // previous iteration's sV/sW consumers done

        // stage all 8 heads' V tiles (bf16 k-pairs): sV[h][d][kp]
        {
            const uint32_t* src = &g_vb[((size_t)b*HH*(SS/2))*HD + (size_t)(kt >> 1)*HD];
            for (int i = tid; i < 8*2048; i += 256) {
                int h = i >> 11, kp = (i >> 6) & 31, d = i & 63;
                sV[h*2112 + d*33 + kp] =
                    g_vb[(((size_t)b*HH + h)*(SS/2) + (kt >> 1) + kp)*HD + d];
            }
            (void)src;
        }

        // stream L fragments for all 8 post-mix heads -> P (registers)
        float P[8][16];
        #pragma unroll
        for (int j = 0; j < 8; j++) {
            const float* Lp = &g_sc[(((size_t)b*HH + j)*SS + qt)*SS + kt];
            #pragma unroll
            for (int jt = 0; jt < 4; jt++) {
                int col = n0c + 8*jt + 2*t;
                float2 v0 = *(const float2*)&Lp[(size_t)r0*SS + col];
                float2 v1 = *(const float2*)&Lp[(size_t)r1*SS + col];
                P[j][jt*4+0] = v0.x; P[j][jt*4+1] = v0.y;
                P[j][jt*4+2] = v1.x; P[j][jt*4+3] = v1.y;
            }
        }
        #pragma unroll
        for (int j = 0; j < 8; j++) {
            #pragma unroll
            for (int jt = 0; jt < 4; jt++) {
                P[j][jt*4+0] = __expf(P[j][jt*4+0]) * inv0[j];
                P[j][jt*4+1] = __expf(P[j][jt*4+1]) * inv0[j];
                P[j][jt*4+2] = __expf(P[j][jt*4+2]) * inv1[j];
                P[j][jt*4+3] = __expf(P[j][jt*4+3]) * inv1[j];
            }
        }
        __syncthreads();    // sV ready

        for (int gg = 0; gg < 8; gg++) {
            // W_gg = sum_j ww[gg,j] * P_j  -> bf16 pairs into sW[buf]
            uint32_t* Wb = sW + buf*2112;
            #pragma unroll
            for (int jt = 0; jt < 4; jt++) {
                float w0 = 0.f, w1 = 0.f, w2 = 0.f, w3 = 0.f;
                #pragma unroll
                for (int j = 0; j < 8; j++) {
                    float cj = sww[gg*8 + j];
                    w0 += cj * P[j][jt*4+0];
                    w1 += cj * P[j][jt*4+1];
                    w2 += cj * P[j][jt*4+2];
                    w3 += cj * P[j][jt*4+3];
                }
                int kp = (n0c >> 1) + 4*jt + t;
                Wb[r0*33 + kp] = pack_bf16(w0, w1);
                Wb[r1*33 + kp] = pack_bf16(w2, w3);
            }
            __syncthreads();  // W_gg complete (and sW[buf^1] consumers from gg-1 done)

            // O_gg[q0:q0+16, n0c:n0c+32] += W_gg @ V_gg
            const uint32_t* Vh = sV + gg*2112;
            float o[4][4] = {};
            #pragma unroll
            for (int c = 0; c < 4; c++) {           // k16 chunks
                uint32_t a0 = Wb[(q0 + g    )*33 + c*8 + t];
                uint32_t a1 = Wb[(q0 + g + 8)*33 + c*8 + t];
                uint32_t a2 = Wb[(q0 + g    )*33 + c*8 + t + 4];
                uint32_t a3 = Wb[(q0 + g + 8)*33 + c*8 + t + 4];
                #pragma unroll
                for (int dc = 0; dc < 4; dc++) {    // d8 chunks
                    int d = n0c + dc*8 + g;
                    uint32_t b0 = Vh[d*33 + c*8 + t];
                    uint32_t b1 = Vh[d*33 + c*8 + t + 4];
                    mma_bf16(o[dc], a0, a1, a2, a3, b0, b1);
                }
            }
            float* Og = sO + gg*4160;               // 64*65
            #pragma unroll
            for (int dc = 0; dc < 4; dc++) {
                int col = n0c + dc*8 + 2*t;
                Og[r0*65 + col]     += o[dc][0];
                Og[r0*65 + col + 1] += o[dc][1];
                Og[r1*65 + col]     += o[dc][2];
                Og[r1*65 + col + 1] += o[dc][3];
            }
            buf ^= 1;
        }
    }

    // epilogue: + b_w[g]*colsum(V_g) -> g_ao[b, q, g*64+d]
    __syncthreads();
    for (int i = tid; i < 32768; i += 256) {
        int gg = i >> 12, q = (i >> 6) & 63, d = i & 63;
        float vs = g_vs[((size_t)b*HH + gg)*HD + d];
        g_ao[((size_t)b*SS + qt + q)*DD + gg*64 + d] = sO[gg*4160 + q*65 + d] + sbw[gg]*vs;
    }
}

// ============================================================================
// Kernel 5: output projection (tf32 mma).
// ============================================================================
__global__ __launch_bounds__(256) void k_proj(const float* __restrict__ w,
                                              const float* __restrict__ bias,
                                              float* __restrict__ out) {
    __shared__ uint32_t As[64][68];
    __shared__ uint32_t Bs[64][68];
    const int tid = threadIdx.x;
    const int lane = tid & 31, warp = tid >> 5;
    const int g = lane >> 2, t = lane & 3;
    const int q0 = (warp >> 1) * 16, n0c = (warp & 1) * 32;
    const int m0 = blockIdx.y * 64;
    const int n0 = blockIdx.x * 64;

    float c[4][4] = {};
    for (int k0 = 0; k0 < DD; k0 += 64) {
        stage_tile(As, &g_ao[(size_t)m0 * DD + k0], DD, tid);
        stage_tile(Bs, &w[(size_t)n0 * DD + k0], DD, tid);
        __syncthreads();
        #pragma unroll
        for (int kk = 0; kk < 64; kk += 8) {
            uint32_t a0 = As[q0 + g][kk + t];
            uint32_t a1 = As[q0 + g + 8][kk + t];
            uint32_t a2 = As[q0 + g][kk + t + 4];
            uint32_t a3 = As[q0 + g + 8][kk + t + 4];
            #pragma unroll
            for (int j = 0; j < 4; j++) {
                uint32_t b0 = Bs[n0c + 8*j + g][kk + t];
                uint32_t b1 = Bs[n0c + 8*j + g][kk + t + 4];
                mma_tf32(c[j], a0, a1, a2, a3, b0, b1);
            }
        }
        __syncthreads();
    }
    #pragma unroll
    for (int j = 0; j < 4; j++) {
        int col = n0 + n0c + 8*j + 2*t;
        float2 bv = *(const float2*)&bias[col];
        float2 lo = make_float2(c[j][0] + bv.x, c[j][1] + bv.y);
        float2 hi = make_float2(c[j][2] + bv.x, c[j][3] + bv.y);
        *(float2*)&out[(size_t)(m0 + q0 + g    ) * DD + col] = lo;
        *(float2*)&out[(size_t)(m0 + q0 + g + 8) * DD + col] = hi;
    }
}

// ============================================================================
extern "C" void kernel_launch(void* const* d_in, const int* in_sizes, int n_in,
                              void* d_out, int out_size) {
    const float* x      = (const float*)d_in[0];
    const float* w_qkv  = (const float*)d_in[1];
    const float* w_proj = (const float*)d_in[2];
    const float* b_proj = (const float*)d_in[3];
    const float* w_l    = (const float*)d_in[4];
    const float* b_l    = (const float*)d_in[5];
    const float* w_w    = (const float*)d_in[6];
    const float* b_w    = (const float*)d_in[7];
    float* out = (float*)d_out;

    cudaFuncSetAttribute(k_av_fused, cudaFuncAttributeMaxDynamicSharedMemorySize, SMEM_AV);

    k_qkv   <<<dim3(QKV_N/64, NTOK/64), 256>>>(x, w_qkv);
    k_zero  <<<(BB*HH*SS + 255)/256, 256>>>();
    k_vsum  <<<BB*HH, 256>>>();
    k_packv <<<(BB*HH*(SS/2)*HD + 255)/256, 256>>>();
    k_scores<<<dim3(SS/64, SS/64, BB), 256>>>(w_l, b_l);
    k_av_fused<<<dim3(SS/64, BB), 256, SMEM_AV>>>(w_w, b_w);
    k_proj  <<<dim3(DD/64, NTOK/64), 256>>>(w_proj, b_proj, out);
}

// round 5
// speedup vs baseline: 1.4524x; 1.2961x over previous
#include <cuda_runtime.h>
#include <cuda_bf16.h>
#include <cstdint>

// Problem constants
#define BB   4
#define SS   2048
#define DD   512
#define HH   8
#define HD   64
#define NTOK (BB*SS)          // 8192
#define QKV_N (3*DD)          // 1536
#define SCALE 0.125f          // HD^-0.5

// ---------------- scratch (__device__ globals) ------------------------------
static __device__ float    g_q[BB*HH*SS*HD];           // 16 MB (SCALE applied)
static __device__ float    g_k[BB*HH*SS*HD];           // 16 MB
static __device__ float    g_v[BB*HH*SS*HD];           // 16 MB
static __device__ uint32_t g_vb[BB*HH*HD*(SS/2)];      // 8 MB  [b][h][d][kp] bf16x2
static __device__ uint32_t g_eb[BB*HH*SS*(SS/2)];      // 256 MB E=exp(L) bf16 [b][j][q][kp]
static __device__ uint32_t g_wb[BB*HH*SS*(SS/2)];      // 256 MB mixed W bf16 [b][g][q][kp]
static __device__ float    g_ao[NTOK*DD];              // 16 MB
static __device__ float    g_l[BB*HH*SS];              // softmax denominators
static __device__ float    g_vs[BB*HH*HD];             // colsum of V per (b,h)

// ---------------- helpers ---------------------------------------------------
__device__ __forceinline__ uint32_t f2tf32(float f) {
    uint32_t u;
    asm("cvt.rna.tf32.f32 %0, %1;" : "=r"(u) : "f"(f));
    return u;
}

__device__ __forceinline__ void mma_tf32(float* c,
                                         uint32_t a0, uint32_t a1, uint32_t a2, uint32_t a3,
                                         uint32_t b0, uint32_t b1) {
    asm volatile(
        "mma.sync.aligned.m16n8k8.row.col.f32.tf32.tf32.f32 "
        "{%0,%1,%2,%3}, {%4,%5,%6,%7}, {%8,%9}, {%0,%1,%2,%3};\n"
        : "+f"(c[0]), "+f"(c[1]), "+f"(c[2]), "+f"(c[3])
        : "r"(a0), "r"(a1), "r"(a2), "r"(a3), "r"(b0), "r"(b1));
}

__device__ __forceinline__ void mma_bf16(float* c,
                                         uint32_t a0, uint32_t a1, uint32_t a2, uint32_t a3,
                                         uint32_t b0, uint32_t b1) {
    asm volatile(
        "mma.sync.aligned.m16n8k16.row.col.f32.bf16.bf16.f32 "
        "{%0,%1,%2,%3}, {%4,%5,%6,%7}, {%8,%9}, {%0,%1,%2,%3};\n"
        : "+f"(c[0]), "+f"(c[1]), "+f"(c[2]), "+f"(c[3])
        : "r"(a0), "r"(a1), "r"(a2), "r"(a3), "r"(b0), "r"(b1));
}

__device__ __forceinline__ uint32_t pack_bf16(float lo, float hi) {
    __nv_bfloat162 p = __floats2bfloat162_rn(lo, hi);   // .x = lo (low 16 bits)
    return *reinterpret_cast<uint32_t*>(&p);
}

__device__ __forceinline__ float2 unpack_bf16(uint32_t u) {
    __nv_bfloat162 p = *reinterpret_cast<__nv_bfloat162*>(&u);
    return make_float2(__bfloat162float(p.x), __bfloat162float(p.y));
}

// Stage a 64x64 fp32 tile (row stride ld floats) into tf32 smem [64][68].
__device__ __forceinline__ void stage_tile(uint32_t (*S)[68], const float* __restrict__ src,
                                           size_t ld, int tid) {
    for (int f = tid; f < 1024; f += 256) {
        int r = f >> 4, c = (f & 15) << 2;
        float4 v = *(const float4*)&src[(size_t)r * ld + c];
        uint4 u;
        u.x = f2tf32(v.x); u.y = f2tf32(v.y); u.z = f2tf32(v.z); u.w = f2tf32(v.w);
        *(uint4*)&S[r][c] = u;
    }
}

// ============================================================================
// Kernel 1: QKV GEMM (tf32 mma), epilogue scatters to g_q/g_k/g_v.
// ============================================================================
__global__ __launch_bounds__(256) void k_qkv(const float* __restrict__ x,
                                             const float* __restrict__ w) {
    __shared__ uint32_t As[64][68];
    __shared__ uint32_t Bs[64][68];
    const int tid = threadIdx.x;
    const int lane = tid & 31, warp = tid >> 5;
    const int g = lane >> 2, t = lane & 3;
    const int q0 = (warp >> 1) * 16, n0c = (warp & 1) * 32;
    const int m0 = blockIdx.y * 64;
    const int n0 = blockIdx.x * 64;

    float c[4][4] = {};
    for (int k0 = 0; k0 < DD; k0 += 64) {
        stage_tile(As, &x[(size_t)m0 * DD + k0], DD, tid);
        stage_tile(Bs, &w[(size_t)n0 * DD + k0], DD, tid);
        __syncthreads();
        #pragma unroll
        for (int kk = 0; kk < 64; kk += 8) {
            uint32_t a0 = As[q0 + g][kk + t];
            uint32_t a1 = As[q0 + g + 8][kk + t];
            uint32_t a2 = As[q0 + g][kk + t + 4];
            uint32_t a3 = As[q0 + g + 8][kk + t + 4];
            #pragma unroll
            for (int j = 0; j < 4; j++) {
                uint32_t b0 = Bs[n0c + 8*j + g][kk + t];
                uint32_t b1 = Bs[n0c + 8*j + g][kk + t + 4];
                mma_tf32(c[j], a0, a1, a2, a3, b0, b1);
            }
        }
        __syncthreads();
    }
    const int which = n0 >> 9;
    const int h     = (n0 >> 6) & 7;
    const int b     = m0 / SS;
    const int sbase = m0 % SS;
    float* dst = (which == 0) ? g_q : (which == 1) ? g_k : g_v;
    const float mul = (which == 0) ? SCALE : 1.0f;
    #pragma unroll
    for (int j = 0; j < 4; j++) {
        int col = n0c + 8*j + 2*t;
        float2 lo = make_float2(c[j][0]*mul, c[j][1]*mul);
        float2 hi = make_float2(c[j][2]*mul, c[j][3]*mul);
        *(float2*)&dst[(((size_t)b*HH + h)*SS + sbase + q0 + g    )*HD + col] = lo;
        *(float2*)&dst[(((size_t)b*HH + h)*SS + sbase + q0 + g + 8)*HD + col] = hi;
    }
}

// ============================================================================
// Kernel 2a: zero softmax-denominator accumulator.
// ============================================================================
__global__ __launch_bounds__(256) void k_zero() {
    int i = blockIdx.x * 256 + threadIdx.x;
    if (i < BB*HH*SS) g_l[i] = 0.f;
}

// ============================================================================
// Kernel 2b: V column sums (for b_w bias term). grid = BB*HH.
// ============================================================================
__global__ __launch_bounds__(256) void k_vsum() {
    __shared__ float red[4][64];
    const int tid = threadIdx.x;
    const int bh = blockIdx.x;
    const int d = tid & 63, seg = tid >> 6;
    const float* vp = &g_v[(size_t)bh * SS * HD];
    float s = 0.f;
    for (int r = seg*512; r < (seg+1)*512; r++) s += vp[(size_t)r*HD + d];
    red[seg][d] = s;
    __syncthreads();
    if (tid < 64)
        g_vs[(size_t)bh*HD + tid] = red[0][tid] + red[1][tid] + red[2][tid] + red[3][tid];
}

// ============================================================================
// Kernel 2c: transpose+pack V -> g_vb[b][h][d][kp] bf16 k-pairs.
// Block = (bh, kt64). smem transpose for coalesced r/w.
// ============================================================================
__global__ __launch_bounds__(256) void k_packv() {
    __shared__ float sT[64][65];
    const int tid = threadIdx.x;
    const int bh = blockIdx.x;
    const int kt = blockIdx.y * 64;
    const float* vp = &g_v[((size_t)bh*SS + kt)*HD];
    for (int i = tid; i < 1024; i += 256) {
        int r = i >> 4, c = (i & 15) << 2;
        float4 v = *(const float4*)&vp[(size_t)r*HD + c];
        sT[r][c] = v.x; sT[r][c+1] = v.y; sT[r][c+2] = v.z; sT[r][c+3] = v.w;
    }
    __syncthreads();
    for (int i = tid; i < 2048; i += 256) {
        int kp = i & 31, d = i >> 5;
        g_vb[((size_t)bh*HD + d)*(SS/2) + (kt >> 1) + kp] =
            pack_bf16(sT[2*kp][d], sT[2*kp+1][d]);
    }
}

// ============================================================================
// Kernel 3: scores + pre-mix (tf32 mma). Stores E = exp(L + b_l) in bf16 and
// atomically accumulates denominators l_j[q] (fp32).
// ============================================================================
__global__ __launch_bounds__(256, 1) void k_scores(const float* __restrict__ wl,
                                                   const float* __restrict__ bl) {
    __shared__ uint32_t Qs[64][68];
    __shared__ uint32_t Ks[64][68];
    __shared__ float s_wl[64];
    const int tid = threadIdx.x;
    const int lane = tid & 31, warp = tid >> 5;
    const int g = lane >> 2, t = lane & 3;
    const int q0 = (warp >> 1) * 16, n0c = (warp & 1) * 32;
    const int kt = blockIdx.x * 64;
    const int qt = blockIdx.y * 64;
    const int b  = blockIdx.z;

    if (tid < 64) s_wl[tid] = wl[tid];

    float blr[8];
    #pragma unroll
    for (int j = 0; j < 8; j++) blr[j] = __ldg(&bl[j]);

    float acc[8][16];
    #pragma unroll
    for (int gg = 0; gg < 8; gg++)
        #pragma unroll
        for (int e = 0; e < 16; e++) acc[gg][e] = 0.f;

    for (int h = 0; h < 8; h++) {
        __syncthreads();
        stage_tile(Qs, &g_q[(((size_t)b*HH + h)*SS + qt)*HD], HD, tid);
        stage_tile(Ks, &g_k[(((size_t)b*HH + h)*SS + kt)*HD], HD, tid);
        __syncthreads();
        float s[16] = {};
        #pragma unroll
        for (int kk = 0; kk < 64; kk += 8) {
            uint32_t a0 = Qs[q0 + g][kk + t];
            uint32_t a1 = Qs[q0 + g + 8][kk + t];
            uint32_t a2 = Qs[q0 + g][kk + t + 4];
            uint32_t a3 = Qs[q0 + g + 8][kk + t + 4];
            #pragma unroll
            for (int jt = 0; jt < 4; jt++) {
                uint32_t b0 = Ks[n0c + 8*jt + g][kk + t];
                uint32_t b1 = Ks[n0c + 8*jt + g][kk + t + 4];
                mma_tf32(&s[jt*4], a0, a1, a2, a3, b0, b1);
            }
        }
        #pragma unroll
        for (int j = 0; j < 8; j++) {
            float wv = s_wl[j*8 + h];
            #pragma unroll
            for (int e = 0; e < 16; e++) acc[j][e] += wv * s[e];
        }
    }
    // epilogue: E = exp(acc + b_l) -> bf16 store; fp32 denominator accumulation
    #pragma unroll
    for (int j = 0; j < 8; j++) {
        float blv = blr[j];
        size_t rb0 = (((size_t)b*HH + j)*SS + qt + q0 + g    ) * (SS/2);
        size_t rb1 = (((size_t)b*HH + j)*SS + qt + q0 + g + 8) * (SS/2);
        float l0 = 0.f, l1 = 0.f;
        #pragma unroll
        for (int jt = 0; jt < 4; jt++) {
            int colp = (kt + n0c + 8*jt) >> 1;          // uint32 (pair) index
            float e0 = __expf(acc[j][jt*4+0] + blv);
            float e1 = __expf(acc[j][jt*4+1] + blv);
            float e2 = __expf(acc[j][jt*4+2] + blv);
            float e3 = __expf(acc[j][jt*4+3] + blv);
            g_eb[rb0 + colp + t] = pack_bf16(e0, e1);
            g_eb[rb1 + colp + t] = pack_bf16(e2, e3);
            l0 += e0 + e1;
            l1 += e2 + e3;
        }
        l0 += __shfl_xor_sync(0xffffffffu, l0, 1);
        l0 += __shfl_xor_sync(0xffffffffu, l0, 2);
        l1 += __shfl_xor_sync(0xffffffffu, l1, 1);
        l1 += __shfl_xor_sync(0xffffffffu, l1, 2);
        if (t == 0) {
            atomicAdd(&g_l[((size_t)b*HH + j)*SS + qt + q0 + g    ], l0);
            atomicAdd(&g_l[((size_t)b*HH + j)*SS + qt + q0 + g + 8], l1);
        }
    }
}

// ============================================================================
// Kernel 4: post-softmax mix, streaming. Block = (b, q); reads E_j row (bf16),
// writes W_g = sum_j (ww[g,j]/l_j) E_j (bf16). High occupancy, no heavy syncs.
// ============================================================================
__global__ __launch_bounds__(256) void k_mix(const float* __restrict__ ww) {
    __shared__ float s_c[8][8];          // c[g][j] = ww[g,j] * inv_l[j]
    const int tid = threadIdx.x;
    const int q = blockIdx.x & (SS-1);
    const int b = blockIdx.x >> 11;

    __shared__ float s_inv[8];
    if (tid < 8) s_inv[tid] = 1.0f / g_l[((size_t)b*HH + tid)*SS + q];
    __syncthreads();
    if (tid < 64) s_c[tid >> 3][tid & 7] = ww[tid] * s_inv[tid & 7];
    __syncthreads();

    const size_t rbase = ((size_t)b*HH*SS + q) * (SS/2);   // + j*SS*(SS/2)
    #pragma unroll
    for (int p = 0; p < 4; p++) {
        int pos = p*256 + tid;
        float elo[8], ehi[8];
        #pragma unroll
        for (int j = 0; j < 8; j++) {
            float2 e = unpack_bf16(g_eb[rbase + (size_t)j*SS*(SS/2) + pos]);
            elo[j] = e.x; ehi[j] = e.y;
        }
        #pragma unroll
        for (int g = 0; g < 8; g++) {
            float wlo = 0.f, whi = 0.f;
            #pragma unroll
            for (int j = 0; j < 8; j++) {
                wlo += s_c[g][j] * elo[j];
                whi += s_c[g][j] * ehi[j];
            }
            g_wb[rbase + (size_t)g*SS*(SS/2) + pos] = pack_bf16(wlo, whi);
        }
    }
}

// ============================================================================
// Kernel 5: AV GEMM (bf16 mma). CTA = (h=g, qt, b), 64x64 out, k-loop 2048.
// A = W bf16 [q][kp], B = V bf16 [d][kp]. Small smem -> high occupancy.
// ============================================================================
__global__ __launch_bounds__(256) void k_av(const float* __restrict__ bw) {
    __shared__ uint32_t sW[64][33];
    __shared__ uint32_t sV[64][33];
    const int tid = threadIdx.x;
    const int lane = tid & 31, warp = tid >> 5;
    const int g = lane >> 2, t = lane & 3;
    const int q0 = (warp >> 1) * 16, n0c = (warp & 1) * 32;
    const int h  = blockIdx.x;
    const int qt = blockIdx.y * 64;
    const int b  = blockIdx.z;
    const int r0 = q0 + g, r1 = r0 + 8;

    const uint32_t* Wp = &g_wb[(((size_t)b*HH + h)*SS + qt) * (SS/2)];
    const uint32_t* Vp = &g_vb[((size_t)b*HH + h)*HD*(SS/2)];

    float c[4][4] = {};
    for (int k0 = 0; k0 < SS; k0 += 64) {
        const int kp0 = k0 >> 1;
        for (int i = tid; i < 2048; i += 256) {
            int r = i >> 5, cc = i & 31;
            sW[r][cc] = Wp[(size_t)r*(SS/2) + kp0 + cc];
            sV[r][cc] = Vp[(size_t)r*(SS/2) + kp0 + cc];
        }
        __syncthreads();
        #pragma unroll
        for (int ck = 0; ck < 4; ck++) {                 // four k16 chunks
            uint32_t a0 = sW[r0][ck*8 + t];
            uint32_t a1 = sW[r1][ck*8 + t];
            uint32_t a2 = sW[r0][ck*8 + t + 4];
            uint32_t a3 = sW[r1][ck*8 + t + 4];
            #pragma unroll
            for (int dc = 0; dc < 4; dc++) {             // four n8 chunks
                int d = n0c + dc*8 + g;
                uint32_t b0 = sV[d][ck*8 + t];
                uint32_t b1 = sV[d][ck*8 + t + 4];
                mma_bf16(c[dc], a0, a1, a2, a3, b0, b1);
            }
        }
        __syncthreads();
    }
    // epilogue: + b_w[h]*colsum(V_h) -> g_ao[b, q, h*64+d]
    const float bwv = __ldg(&bw[h]);
    #pragma unroll
    for (int dc = 0; dc < 4; dc++) {
        int col = n0c + dc*8 + 2*t;
        float vs0 = g_vs[((size_t)b*HH + h)*HD + col];
        float vs1 = g_vs[((size_t)b*HH + h)*HD + col + 1];
        float2 lo = make_float2(c[dc][0] + bwv*vs0, c[dc][1] + bwv*vs1);
        float2 hi = make_float2(c[dc][2] + bwv*vs0, c[dc][3] + bwv*vs1);
        *(float2*)&g_ao[((size_t)b*SS + qt + r0)*DD + h*64 + col] = lo;
        *(float2*)&g_ao[((size_t)b*SS + qt + r1)*DD + h*64 + col] = hi;
    }
}

// ============================================================================
// Kernel 6: output projection (tf32 mma).
// ============================================================================
__global__ __launch_bounds__(256) void k_proj(const float* __restrict__ w,
                                              const float* __restrict__ bias,
                                              float* __restrict__ out) {
    __shared__ uint32_t As[64][68];
    __shared__ uint32_t Bs[64][68];
    const int tid = threadIdx.x;
    const int lane = tid & 31, warp = tid >> 5;
    const int g = lane >> 2, t = lane & 3;
    const int q0 = (warp >> 1) * 16, n0c = (warp & 1) * 32;
    const int m0 = blockIdx.y * 64;
    const int n0 = blockIdx.x * 64;

    float c[4][4] = {};
    for (int k0 = 0; k0 < DD; k0 += 64) {
        stage_tile(As, &g_ao[(size_t)m0 * DD + k0], DD, tid);
        stage_tile(Bs, &w[(size_t)n0 * DD + k0], DD, tid);
        __syncthreads();
        #pragma unroll
        for (int kk = 0; kk < 64; kk += 8) {
            uint32_t a0 = As[q0 + g][kk + t];
            uint32_t a1 = As[q0 + g + 8][kk + t];
            uint32_t a2 = As[q0 + g][kk + t + 4];
            uint32_t a3 = As[q0 + g + 8][kk + t + 4];
            #pragma unroll
            for (int j = 0; j < 4; j++) {
                uint32_t b0 = Bs[n0c + 8*j + g][kk + t];
                uint32_t b1 = Bs[n0c + 8*j + g][kk + t + 4];
                mma_tf32(c[j], a0, a1, a2, a3, b0, b1);
            }
        }
        __syncthreads();
    }
    #pragma unroll
    for (int j = 0; j < 4; j++) {
        int col = n0 + n0c + 8*j + 2*t;
        float2 bv = *(const float2*)&bias[col];
        float2 lo = make_float2(c[j][0] + bv.x, c[j][1] + bv.y);
        float2 hi = make_float2(c[j][2] + bv.x, c[j][3] + bv.y);
        *(float2*)&out[(size_t)(m0 + q0 + g    ) * DD + col] = lo;
        *(float2*)&out[(size_t)(m0 + q0 + g + 8) * DD + col] = hi;
    }
}

// ============================================================================
extern "C" void kernel_launch(void* const* d_in, const int* in_sizes, int n_in,
                              void* d_out, int out_size) {
    const float* x      = (const float*)d_in[0];
    const float* w_qkv  = (const float*)d_in[1];
    const float* w_proj = (const float*)d_in[2];
    const float* b_proj = (const float*)d_in[3];
    const float* w_l    = (const float*)d_in[4];
    const float* b_l    = (const float*)d_in[5];
    const float* w_w    = (const float*)d_in[6];
    const float* b_w    = (const float*)d_in[7];
    float* out = (float*)d_out;

    k_qkv   <<<dim3(QKV_N/64, NTOK/64), 256>>>(x, w_qkv);
    k_zero  <<<(BB*HH*SS + 255)/256, 256>>>();
    k_vsum  <<<BB*HH, 256>>>();
    k_packv <<<dim3(BB*HH, SS/64), 256>>>();
    k_scores<<<dim3(SS/64, SS/64, BB), 256>>>(w_l, b_l);
    k_mix   <<<BB*SS, 256>>>(w_w);
    k_av    <<<dim3(HH, SS/64, BB), 256>>>(b_w);
    k_proj  <<<dim3(DD/64, NTOK/64), 256>>>(w_proj, b_proj, out);
}

// round 7
// speedup vs baseline: 2.6762x; 1.8426x over previous
#include <cuda_runtime.h>
#include <cuda_bf16.h>
#include <cstdint>

// Problem constants
#define BB   4
#define SS   2048
#define DD   512
#define HH   8
#define HD   64
#define NTOK (BB*SS)          // 8192
#define QKV_N (3*DD)          // 1536
#define SCALE 0.125f          // HD^-0.5

// ---------------- scratch (__device__ globals) ------------------------------
static __device__ uint32_t g_qb[BB*HH*SS*(HD/2)];      // 8 MB Q bf16 pairs [bh][s][dp]
static __device__ uint32_t g_kb[BB*HH*SS*(HD/2)];      // 8 MB K bf16 pairs [bh][s][dp]
static __device__ float    g_v [BB*HH*SS*HD];          // 16 MB fp32
static __device__ uint32_t g_vb[BB*HH*HD*(SS/2)];      // 8 MB V bf16 pairs [bh][d][kp]
static __device__ uint32_t g_eb[BB*HH*SS*(SS/2)];      // 256 MB E bf16 [b][j][q][kp]
static __device__ uint32_t g_wb[BB*HH*SS*(SS/2)];      // 256 MB W bf16 [b][g][q][kp]
static __device__ float    g_ao[NTOK*DD];              // 16 MB
static __device__ float    g_l[BB*HH*SS];              // softmax denominators
static __device__ float    g_vs[BB*HH*HD];             // colsum of V per (b,h)

// ---------------- helpers ---------------------------------------------------
__device__ __forceinline__ uint32_t f2tf32(float f) {
    uint32_t u;
    asm("cvt.rna.tf32.f32 %0, %1;" : "=r"(u) : "f"(f));
    return u;
}

__device__ __forceinline__ void mma_tf32(float* c,
                                         uint32_t a0, uint32_t a1, uint32_t a2, uint32_t a3,
                                         uint32_t b0, uint32_t b1) {
    asm volatile(
        "mma.sync.aligned.m16n8k8.row.col.f32.tf32.tf32.f32 "
        "{%0,%1,%2,%3}, {%4,%5,%6,%7}, {%8,%9}, {%0,%1,%2,%3};\n"
        : "+f"(c[0]), "+f"(c[1]), "+f"(c[2]), "+f"(c[3])
        : "r"(a0), "r"(a1), "r"(a2), "r"(a3), "r"(b0), "r"(b1));
}

__device__ __forceinline__ void mma_bf16(float* c,
                                         uint32_t a0, uint32_t a1, uint32_t a2, uint32_t a3,
                                         uint32_t b0, uint32_t b1) {
    asm volatile(
        "mma.sync.aligned.m16n8k16.row.col.f32.bf16.bf16.f32 "
        "{%0,%1,%2,%3}, {%4,%5,%6,%7}, {%8,%9}, {%0,%1,%2,%3};\n"
        : "+f"(c[0]), "+f"(c[1]), "+f"(c[2]), "+f"(c[3])
        : "r"(a0), "r"(a1), "r"(a2), "r"(a3), "r"(b0), "r"(b1));
}

__device__ __forceinline__ uint32_t pack_bf16(float lo, float hi) {
    __nv_bfloat162 p = __floats2bfloat162_rn(lo, hi);
    return *reinterpret_cast<uint32_t*>(&p);
}

__device__ __forceinline__ float2 unpack_bf16(uint32_t u) {
    __nv_bfloat162 p = *reinterpret_cast<__nv_bfloat162*>(&u);
    return make_float2(__bfloat162float(p.x), __bfloat162float(p.y));
}

// Stage a 64x64 fp32 tile (row stride ld floats) into tf32 smem [64][68].
__device__ __forceinline__ void stage_tile(uint32_t (*S)[68], const float* __restrict__ src,
                                           size_t ld, int tid) {
    for (int f = tid; f < 1024; f += 256) {
        int r = f >> 4, c = (f & 15) << 2;
        float4 v = *(const float4*)&src[(size_t)r * ld + c];
        uint4 u;
        u.x = f2tf32(v.x); u.y = f2tf32(v.y); u.z = f2tf32(v.z); u.w = f2tf32(v.w);
        *(uint4*)&S[r][c] = u;
    }
}

// ============================================================================
// Kernel 1: QKV GEMM (tf32 mma). Q,K -> bf16 pairs; V -> fp32.
// ============================================================================
__global__ __launch_bounds__(256) void k_qkv(const float* __restrict__ x,
                                             const float* __restrict__ w) {
    __shared__ uint32_t As[64][68];
    __shared__ uint32_t Bs[64][68];
    const int tid = threadIdx.x;
    const int lane = tid & 31, warp = tid >> 5;
    const int g = lane >> 2, t = lane & 3;
    const int q0 = (warp >> 1) * 16, n0c = (warp & 1) * 32;
    const int m0 = blockIdx.y * 64;
    const int n0 = blockIdx.x * 64;

    float c[4][4] = {};
    for (int k0 = 0; k0 < DD; k0 += 64) {
        stage_tile(As, &x[(size_t)m0 * DD + k0], DD, tid);
        stage_tile(Bs, &w[(size_t)n0 * DD + k0], DD, tid);
        __syncthreads();
        #pragma unroll
        for (int kk = 0; kk < 64; kk += 8) {
            uint32_t a0 = As[q0 + g][kk + t];
            uint32_t a1 = As[q0 + g + 8][kk + t];
            uint32_t a2 = As[q0 + g][kk + t + 4];
            uint32_t a3 = As[q0 + g + 8][kk + t + 4];
            #pragma unroll
            for (int j = 0; j < 4; j++) {
                uint32_t b0 = Bs[n0c + 8*j + g][kk + t];
                uint32_t b1 = Bs[n0c + 8*j + g][kk + t + 4];
                mma_tf32(c[j], a0, a1, a2, a3, b0, b1);
            }
        }
        __syncthreads();
    }
    const int which = n0 >> 9;
    const int h     = (n0 >> 6) & 7;
    const int b     = m0 / SS;
    const int sbase = m0 % SS;
    const size_t bh = (size_t)b*HH + h;
    if (which == 2) {
        #pragma unroll
        for (int j = 0; j < 4; j++) {
            int col = n0c + 8*j + 2*t;
            *(float2*)&g_v[(bh*SS + sbase + q0 + g    )*HD + col] = make_float2(c[j][0], c[j][1]);
            *(float2*)&g_v[(bh*SS + sbase + q0 + g + 8)*HD + col] = make_float2(c[j][2], c[j][3]);
        }
    } else {
        uint32_t* dst = (which == 0) ? g_qb : g_kb;
        const float mul = (which == 0) ? SCALE : 1.0f;
        #pragma unroll
        for (int j = 0; j < 4; j++) {
            int dp = (n0c + 8*j + 2*t) >> 1;
            dst[(bh*SS + sbase + q0 + g    )*(HD/2) + dp] = pack_bf16(c[j][0]*mul, c[j][1]*mul);
            dst[(bh*SS + sbase + q0 + g + 8)*(HD/2) + dp] = pack_bf16(c[j][2]*mul, c[j][3]*mul);
        }
    }
}

// ============================================================================
// Kernel 2a: zero softmax-denominator accumulator.
// ============================================================================
__global__ __launch_bounds__(256) void k_zero() {
    int i = blockIdx.x * 256 + threadIdx.x;
    if (i < BB*HH*SS) g_l[i] = 0.f;
}

// ============================================================================
// Kernel 2b: V column sums. grid = BB*HH.
// ============================================================================
__global__ __launch_bounds__(256) void k_vsum() {
    __shared__ float red[4][64];
    const int tid = threadIdx.x;
    const int bh = blockIdx.x;
    const int d = tid & 63, seg = tid >> 6;
    const float* vp = &g_v[(size_t)bh * SS * HD];
    float s = 0.f;
    for (int r = seg*512; r < (seg+1)*512; r++) s += vp[(size_t)r*HD + d];
    red[seg][d] = s;
    __syncthreads();
    if (tid < 64)
        g_vs[(size_t)bh*HD + tid] = red[0][tid] + red[1][tid] + red[2][tid] + red[3][tid];
}

// ============================================================================
// Kernel 2c: transpose+pack V -> g_vb[b][h][d][kp] bf16 k-pairs.
// ============================================================================
__global__ __launch_bounds__(256) void k_packv() {
    __shared__ float sT[64][65];
    const int tid = threadIdx.x;
    const int bh = blockIdx.x;
    const int kt = blockIdx.y * 64;
    const float* vp = &g_v[((size_t)bh*SS + kt)*HD];
    for (int i = tid; i < 1024; i += 256) {
        int r = i >> 4, c = (i & 15) << 2;
        float4 v = *(const float4*)&vp[(size_t)r*HD + c];
        sT[r][c] = v.x; sT[r][c+1] = v.y; sT[r][c+2] = v.z; sT[r][c+3] = v.w;
    }
    __syncthreads();
    for (int i = tid; i < 2048; i += 256) {
        int kp = i & 31, d = i >> 5;
        g_vb[((size_t)bh*HD + d)*(SS/2) + (kt >> 1) + kp] =
            pack_bf16(sT[2*kp][d], sT[2*kp+1][d]);
    }
}

// ============================================================================
// Kernel 3: scores + pre-mix (bf16 mma, 32x64 tile, occ 2, double-buffered).
// Stores E = exp(L + b_l) bf16 and accumulates denominators l_j[q].
// grid = (SS/64 kt, SS/32 q-strip, BB).
// ============================================================================
#define SQ_STRIDE 36
__global__ __launch_bounds__(256, 2) void k_scores(const float* __restrict__ wl,
                                                   const float* __restrict__ bl) {
    __shared__ uint32_t sQ[2][32*SQ_STRIDE];
    __shared__ uint32_t sK[2][64*SQ_STRIDE];
    __shared__ float s_wl[64];
    const int tid = threadIdx.x;
    const int lane = tid & 31, warp = tid >> 5;
    const int g = lane >> 2, t = lane & 3;
    const int q0 = (warp >> 2) * 16;        // 0 or 16 (32-row strip)
    const int n0 = (warp & 3) * 16;         // 0,16,32,48
    const int kt = blockIdx.x * 64;
    const int qt = blockIdx.y * 32;
    const int b  = blockIdx.z;

    if (tid < 64) s_wl[tid] = wl[tid];

    float blr[8];
    #pragma unroll
    for (int j = 0; j < 8; j++) blr[j] = __ldg(&bl[j]);

    const int qr = tid >> 3, qc = (tid & 7) * 4;        // Q: 32 rows x 32 pairs
    const int kr = tid >> 2, kc = (tid & 3) * 8;        // K: 64 rows x 32 pairs

    float acc[8][8];
    #pragma unroll
    for (int j = 0; j < 8; j++)
        #pragma unroll
        for (int e = 0; e < 8; e++) acc[j][e] = 0.f;

    // stage head 0
    {
        const uint32_t* Qp = &g_qb[(((size_t)b*HH + 0)*SS + qt)*(HD/2)];
        const uint32_t* Kp = &g_kb[(((size_t)b*HH + 0)*SS + kt)*(HD/2)];
        *(uint4*)&sQ[0][qr*SQ_STRIDE + qc] = *(const uint4*)&Qp[qr*32 + qc];
        *(uint4*)&sK[0][kr*SQ_STRIDE + kc    ] = *(const uint4*)&Kp[kr*32 + kc];
        *(uint4*)&sK[0][kr*SQ_STRIDE + kc + 4] = *(const uint4*)&Kp[kr*32 + kc + 4];
    }

    for (int h = 0; h < 8; h++) {
        __syncthreads();
        if (h < 7) {
            const int nb = (h+1) & 1;
            const uint32_t* Qp = &g_qb[(((size_t)b*HH + h+1)*SS + qt)*(HD/2)];
            const uint32_t* Kp = &g_kb[(((size_t)b*HH + h+1)*SS + kt)*(HD/2)];
            *(uint4*)&sQ[nb][qr*SQ_STRIDE + qc] = *(const uint4*)&Qp[qr*32 + qc];
            *(uint4*)&sK[nb][kr*SQ_STRIDE + kc    ] = *(const uint4*)&Kp[kr*32 + kc];
            *(uint4*)&sK[nb][kr*SQ_STRIDE + kc + 4] = *(const uint4*)&Kp[kr*32 + kc + 4];
        }
        const int cb = h & 1;
        float s[2][4] = {};
        #pragma unroll
        for (int ck = 0; ck < 4; ck++) {
            uint32_t a0 = sQ[cb][(q0 + g    )*SQ_STRIDE + ck*8 + t];
            uint32_t a1 = sQ[cb][(q0 + g + 8)*SQ_STRIDE + ck*8 + t];
            uint32_t a2 = sQ[cb][(q0 + g    )*SQ_STRIDE + ck*8 + t + 4];
            uint32_t a3 = sQ[cb][(q0 + g + 8)*SQ_STRIDE + ck*8 + t + 4];
            #pragma unroll
            for (int jt = 0; jt < 2; jt++) {
                uint32_t b0 = sK[cb][(n0 + jt*8 + g)*SQ_STRIDE + ck*8 + t];
                uint32_t b1 = sK[cb][(n0 + jt*8 + g)*SQ_STRIDE + ck*8 + t + 4];
                mma_bf16(s[jt], a0, a1, a2, a3, b0, b1);
            }
        }
        #pragma unroll
        for (int j = 0; j < 8; j++) {
            float wv = s_wl[j*8 + h];
            #pragma unroll
            for (int jt = 0; jt < 2; jt++)
                #pragma unroll
                for (int e = 0; e < 4; e++)
                    acc[j][jt*4+e] += wv * s[jt][e];
        }
    }

    // epilogue: E = exp(acc + b_l) -> bf16; accumulate denominators
    const int r0 = qt + q0 + g, r1 = r0 + 8;
    #pragma unroll
    for (int j = 0; j < 8; j++) {
        float blv = blr[j];
        size_t rb0 = (((size_t)b*HH + j)*SS + r0) * (SS/2);
        size_t rb1 = (((size_t)b*HH + j)*SS + r1) * (SS/2);
        float l0 = 0.f, l1 = 0.f;
        #pragma unroll
        for (int jt = 0; jt < 2; jt++) {
            int kp = (kt + n0 + jt*8 + 2*t) >> 1;
            float e0 = __expf(acc[j][jt*4+0] + blv);
            float e1 = __expf(acc[j][jt*4+1] + blv);
            float e2 = __expf(acc[j][jt*4+2] + blv);
            float e3 = __expf(acc[j][jt*4+3] + blv);
            g_eb[rb0 + kp] = pack_bf16(e0, e1);
            g_eb[rb1 + kp] = pack_bf16(e2, e3);
            l0 += e0 + e1;
            l1 += e2 + e3;
        }
        l0 += __shfl_xor_sync(0xffffffffu, l0, 1);
        l0 += __shfl_xor_sync(0xffffffffu, l0, 2);
        l1 += __shfl_xor_sync(0xffffffffu, l1, 1);
        l1 += __shfl_xor_sync(0xffffffffu, l1, 2);
        if (t == 0) {
            atomicAdd(&g_l[((size_t)b*HH + j)*SS + r0], l0);
            atomicAdd(&g_l[((size_t)b*HH + j)*SS + r1], l1);
        }
    }
}

// ============================================================================
// Kernel 4: post-softmax mix, streaming (uint2 vectorized).
// ============================================================================
__global__ __launch_bounds__(256) void k_mix(const float* __restrict__ ww) {
    __shared__ float s_c[8][8];
    __shared__ float s_inv[8];
    const int tid = threadIdx.x;
    const int q = blockIdx.x & (SS-1);
    const int b = blockIdx.x >> 11;

    if (tid < 8) s_inv[tid] = 1.0f / g_l[((size_t)b*HH + tid)*SS + q];
    __syncthreads();
    if (tid < 64) s_c[tid >> 3][tid & 7] = ww[tid] * s_inv[tid & 7];
    __syncthreads();

    const size_t rbase = ((size_t)b*HH*SS + q) * (SS/2);
    const uint2* ebase = (const uint2*)g_eb;
    uint2* wbase = (uint2*)g_wb;
    #pragma unroll
    for (int p = 0; p < 2; p++) {
        int pos = p*256 + tid;                           // uint2 index within row (512 total)
        float elo[8][2], ehi[8][2];
        #pragma unroll
        for (int j = 0; j < 8; j++) {
            uint2 e2 = ebase[(rbase + (size_t)j*SS*(SS/2))/2 + pos];
            float2 a = unpack_bf16(e2.x);
            float2 c = unpack_bf16(e2.y);
            elo[j][0] = a.x; ehi[j][0] = a.y;
            elo[j][1] = c.x; ehi[j][1] = c.y;
        }
        #pragma unroll
        for (int g = 0; g < 8; g++) {
            float w0 = 0.f, w1 = 0.f, w2 = 0.f, w3 = 0.f;
            #pragma unroll
            for (int j = 0; j < 8; j++) {
                float cg = s_c[g][j];
                w0 += cg * elo[j][0];
                w1 += cg * ehi[j][0];
                w2 += cg * elo[j][1];
                w3 += cg * ehi[j][1];
            }
            uint2 o;
            o.x = pack_bf16(w0, w1);
            o.y = pack_bf16(w2, w3);
            wbase[(rbase + (size_t)g*SS*(SS/2))/2 + pos] = o;
        }
    }
}

// ============================================================================
// Kernel 5: AV GEMM (bf16 mma, double-buffered). CTA = (h, qt64, b).
// ============================================================================
__global__ __launch_bounds__(256) void k_av(const float* __restrict__ bw) {
    __shared__ uint32_t sW[2][64*SQ_STRIDE];
    __shared__ uint32_t sV[2][64*SQ_STRIDE];
    const int tid = threadIdx.x;
    const int lane = tid & 31, warp = tid >> 5;
    const int g = lane >> 2, t = lane & 3;
    const int q0 = (warp >> 1) * 16, n0c = (warp & 1) * 32;
    const int h  = blockIdx.x;
    const int qt = blockIdx.y * 64;
    const int b  = blockIdx.z;
    const int r0 = q0 + g, r1 = r0 + 8;

    const uint32_t* Wp = &g_wb[(((size_t)b*HH + h)*SS + qt) * (SS/2)];
    const uint32_t* Vp = &g_vb[((size_t)b*HH + h)*HD*(SS/2)];
    const int sr = tid >> 2, sc = (tid & 3) * 8;         // 64 rows x 32 pairs

    // stage kt=0
    *(uint4*)&sW[0][sr*SQ_STRIDE + sc    ] = *(const uint4*)&Wp[(size_t)sr*(SS/2) + sc];
    *(uint4*)&sW[0][sr*SQ_STRIDE + sc + 4] = *(const uint4*)&Wp[(size_t)sr*(SS/2) + sc + 4];
    *(uint4*)&sV[0][sr*SQ_STRIDE + sc    ] = *(const uint4*)&Vp[(size_t)sr*(SS/2) + sc];
    *(uint4*)&sV[0][sr*SQ_STRIDE + sc + 4] = *(const uint4*)&Vp[(size_t)sr*(SS/2) + sc + 4];

    float c[4][4] = {};
    for (int i = 0; i < 32; i++) {
        __syncthreads();
        if (i < 31) {
            const int nb = (i+1) & 1;
            const int kp0 = (i+1) * 32;
            *(uint4*)&sW[nb][sr*SQ_STRIDE + sc    ] = *(const uint4*)&Wp[(size_t)sr*(SS/2) + kp0 + sc];
            *(uint4*)&sW[nb][sr*SQ_STRIDE + sc + 4] = *(const uint4*)&Wp[(size_t)sr*(SS/2) + kp0 + sc + 4];
            *(uint4*)&sV[nb][sr*SQ_STRIDE + sc    ] = *(const uint4*)&Vp[(size_t)sr*(SS/2) + kp0 + sc];
            *(uint4*)&sV[nb][sr*SQ_STRIDE + sc + 4] = *(const uint4*)&Vp[(size_t)sr*(SS/2) + kp0 + sc + 4];
        }
        const int cb = i & 1;
        #pragma unroll
        for (int ck = 0; ck < 4; ck++) {
            uint32_t a0 = sW[cb][r0*SQ_STRIDE + ck*8 + t];
            uint32_t a1 = sW[cb][r1*SQ_STRIDE + ck*8 + t];
            uint32_t a2 = sW[cb][r0*SQ_STRIDE + ck*8 + t + 4];
            uint32_t a3 = sW[cb][r1*SQ_STRIDE + ck*8 + t + 4];
            #pragma unroll
            for (int dc = 0; dc < 4; dc++) {
                int d = n0c + dc*8 + g;
                uint32_t b0 = sV[cb][d*SQ_STRIDE + ck*8 + t];
                uint32_t b1 = sV[cb][d*SQ_STRIDE + ck*8 + t + 4];
                mma_bf16(c[dc], a0, a1, a2, a3, b0, b1);
            }
        }
    }
    // epilogue: + b_w[h]*colsum(V_h) -> g_ao[b, q, h*64+d]
    const float bwv = __ldg(&bw[h]);
    #pragma unroll
    for (int dc = 0; dc < 4; dc++) {
        int col = n0c + dc*8 + 2*t;
        float vs0 = g_vs[((size_t)b*HH + h)*HD + col];
        float vs1 = g_vs[((size_t)b*HH + h)*HD + col + 1];
        float2 lo = make_float2(c[dc][0] + bwv*vs0, c[dc][1] + bwv*vs1);
        float2 hi = make_float2(c[dc][2] + bwv*vs0, c[dc][3] + bwv*vs1);
        *(float2*)&g_ao[((size_t)b*SS + qt + r0)*DD + h*64 + col] = lo;
        *(float2*)&g_ao[((size_t)b*SS + qt + r1)*DD + h*64 + col] = hi;
    }
}

// ============================================================================
// Kernel 6: output projection (tf32 mma).
// ============================================================================
__global__ __launch_bounds__(256) void k_proj(const float* __restrict__ w,
                                              const float* __restrict__ bias,
                                              float* __restrict__ out) {
    __shared__ uint32_t As[64][68];
    __shared__ uint32_t Bs[64][68];
    const int tid = threadIdx.x;
    const int lane = tid & 31, warp = tid >> 5;
    const int g = lane >> 2, t = lane & 3;
    const int q0 = (warp >> 1) * 16, n0c = (warp & 1) * 32;
    const int m0 = blockIdx.y * 64;
    const int n0 = blockIdx.x * 64;

    float c[4][4] = {};
    for (int k0 = 0; k0 < DD; k0 += 64) {
        stage_tile(As, &g_ao[(size_t)m0 * DD + k0], DD, tid);
        stage_tile(Bs, &w[(size_t)n0 * DD + k0], DD, tid);
        __syncthreads();
        #pragma unroll
        for (int kk = 0; kk < 64; kk += 8) {
            uint32_t a0 = As[q0 + g][kk + t];
            uint32_t a1 = As[q0 + g + 8][kk + t];
            uint32_t a2 = As[q0 + g][kk + t + 4];
            uint32_t a3 = As[q0 + g + 8][kk + t + 4];
            #pragma unroll
            for (int j = 0; j < 4; j++) {
                uint32_t b0 = Bs[n0c + 8*j + g][kk + t];
                uint32_t b1 = Bs[n0c + 8*j + g][kk + t + 4];
                mma_tf32(c[j], a0, a1, a2, a3, b0, b1);
            }
        }
        __syncthreads();
    }
    #pragma unroll
    for (int j = 0; j < 4; j++) {
        int col = n0 + n0c + 8*j + 2*t;
        float2 bv = *(const float2*)&bias[col];
        float2 lo = make_float2(c[j][0] + bv.x, c[j][1] + bv.y);
        float2 hi = make_float2(c[j][2] + bv.x, c[j][3] + bv.y);
        *(float2*)&out[(size_t)(m0 + q0 + g    ) * DD + col] = lo;
        *(float2*)&out[(size_t)(m0 + q0 + g + 8) * DD + col] = hi;
    }
}

// ============================================================================
extern "C" void kernel_launch(void* const* d_in, const int* in_sizes, int n_in,
                              void* d_out, int out_size) {
    const float* x      = (const float*)d_in[0];
    const float* w_qkv  = (const float*)d_in[1];
    const float* w_proj = (const float*)d_in[2];
    const float* b_proj = (const float*)d_in[3];
    const float* w_l    = (const float*)d_in[4];
    const float* b_l    = (const float*)d_in[5];
    const float* w_w    = (const float*)d_in[6];
    const float* b_w    = (const float*)d_in[7];
    float* out = (float*)d_out;

    k_qkv   <<<dim3(QKV_N/64, NTOK/64), 256>>>(x, w_qkv);
    k_zero  <<<(BB*HH*SS + 255)/256, 256>>>();
    k_vsum  <<<BB*HH, 256>>>();
    k_packv <<<dim3(BB*HH, SS/64), 256>>>();
    k_scores<<<dim3(SS/64, SS/32, BB), 256>>>(w_l, b_l);
    k_mix   <<<BB*SS, 256>>>(w_w);
    k_av    <<<dim3(HH, SS/64, BB), 256>>>(b_w);
    k_proj  <<<dim3(DD/64, NTOK/64), 256>>>(w_proj, b_proj, out);
}